// round 8
// baseline (speedup 1.0000x reference)
#include <cuda_runtime.h>

#define B_ 64
#define S_ 512
#define I_ 256
#define O_ 256

typedef unsigned long long ULL;

// Scratch: xg[m][n], m = s*64 + b (32768), n = gate*256 + o (1024). 134 MB.
__device__ float g_xg[(size_t)S_ * B_ * 4 * O_];

// ---------------------------------------------------------------------------
// helpers
// ---------------------------------------------------------------------------
__device__ __forceinline__ ULL ffma2(ULL a, ULL b, ULL c) {
    ULL d;
    asm("fma.rn.f32x2 %0, %1, %2, %3;" : "=l"(d) : "l"(a), "l"(b), "l"(c));
    return d;
}
__device__ __forceinline__ float f2lo(ULL v) { return __uint_as_float((unsigned)v); }
__device__ __forceinline__ float f2hi(ULL v) { return __uint_as_float((unsigned)(v >> 32)); }
__device__ __forceinline__ float sigf(float x) { return 1.0f / (1.0f + __expf(-x)); }
__device__ __forceinline__ float tanhx(float x) { return 2.0f * sigf(2.0f * x) - 1.0f; }
__device__ __forceinline__ unsigned smem_u32(const void* p) {
    return (unsigned)__cvta_generic_to_shared(p);
}
__device__ __forceinline__ void dsmem_st_f32(unsigned local_addr, int rank, float v) {
    unsigned ra;
    asm volatile("mapa.shared::cluster.u32 %0, %1, %2;"
                 : "=r"(ra) : "r"(local_addr), "r"(rank));
    asm volatile("st.shared::cluster.f32 [%0], %1;" :: "r"(ra), "f"(v) : "memory");
}
__device__ __forceinline__ void mbar_arrive_rank(unsigned local_mbar, int rank) {
    asm volatile(
        "{\n\t.reg .b32 ra;\n\t"
        "mapa.shared::cluster.u32 ra, %0, %1;\n\t"
        "mbarrier.arrive.release.cluster.shared::cluster.b64 _, [ra];\n\t}"
        :: "r"(local_mbar), "r"(rank) : "memory");
}
__device__ __forceinline__ void mbar_wait_cluster(unsigned mbar, unsigned parity) {
    asm volatile(
        "{\n\t.reg .pred P1;\n\t"
        "WAIT_%=:\n\t"
        "mbarrier.try_wait.parity.acquire.cluster.shared::cta.b64 P1, [%0], %1, 0x989680;\n\t"
        "@P1 bra.uni DONE_%=;\n\t"
        "bra.uni WAIT_%=;\n\t"
        "DONE_%=:\n\t}"
        :: "r"(mbar), "r"(parity) : "memory");
}

// ---------------------------------------------------------------------------
// Phase 1: xg[m][n] = sum_i x[b,s,i] * Wx[n,i] + bx[n] + bh[n]
//   M=32768 (m=s*64+b), N=1024, K=256. BM=BN=128, BK=16, 256 thr, 8x8 tile.
// ---------------------------------------------------------------------------
__global__ void __launch_bounds__(256, 1) gemm_xg_kernel(
    const float* __restrict__ x, const float* __restrict__ Wx,
    const float* __restrict__ bx, const float* __restrict__ bh) {
    __shared__ __align__(16) float As[128][20];
    __shared__ __align__(16) float Bs[128][20];

    const int t  = threadIdx.x;
    const int bn = blockIdx.x;   // 0..7
    const int bm = blockIdx.y;   // 0..255
    const int tx = t & 15;
    const int ty = t >> 4;

    const int arow  = t & 127;
    const int ahalf = (t >> 7) * 8;            // 0 or 8
    const int m_l   = bm * 128 + arow;
    const float* arp = x + ((size_t)(m_l & 63) * S_ + (m_l >> 6)) * I_ + ahalf;
    const int brow  = t & 127;
    const int bhalf = (t >> 7) * 8;
    const float* brp = Wx + (size_t)(bn * 128 + brow) * I_ + bhalf;

    ULL acc[8][8];
#pragma unroll
    for (int i = 0; i < 8; ++i)
#pragma unroll
        for (int j = 0; j < 8; ++j) acc[i][j] = 0ULL;

    float4 pa0 = *(const float4*)(arp + 0);
    float4 pa1 = *(const float4*)(arp + 4);
    float4 pb0 = *(const float4*)(brp + 0);
    float4 pb1 = *(const float4*)(brp + 4);

    for (int kt = 0; kt < I_; kt += 16) {
        __syncthreads();
        *(float4*)&As[arow][ahalf]     = pa0;
        *(float4*)&As[arow][ahalf + 4] = pa1;
        *(float4*)&Bs[brow][bhalf]     = pb0;
        *(float4*)&Bs[brow][bhalf + 4] = pb1;
        __syncthreads();
        if (kt + 16 < I_) {
            pa0 = *(const float4*)(arp + kt + 16);
            pa1 = *(const float4*)(arp + kt + 20);
            pb0 = *(const float4*)(brp + kt + 16);
            pb1 = *(const float4*)(brp + kt + 20);
        }
#pragma unroll
        for (int k4 = 0; k4 < 4; ++k4) {
            ulonglong2 a2[8];
#pragma unroll
            for (int i = 0; i < 8; ++i)
                a2[i] = *(const ulonglong2*)&As[ty + i * 16][k4 * 4];
#pragma unroll
            for (int j = 0; j < 8; ++j) {
                ulonglong2 b2 = *(const ulonglong2*)&Bs[tx + j * 16][k4 * 4];
#pragma unroll
                for (int i = 0; i < 8; ++i) {
                    acc[i][j] = ffma2(a2[i].x, b2.x, acc[i][j]);
                    acc[i][j] = ffma2(a2[i].y, b2.y, acc[i][j]);
                }
            }
        }
    }

#pragma unroll
    for (int j = 0; j < 8; ++j) {
        const int n = bn * 128 + tx + j * 16;
        const float bias = bx[n] + bh[n];
#pragma unroll
        for (int i = 0; i < 8; ++i) {
            const int m = bm * 128 + ty + i * 16;
            g_xg[(size_t)m * 1024 + n] = f2lo(acc[i][j]) + f2hi(acc[i][j]) + bias;
        }
    }
}

// ---------------------------------------------------------------------------
// Phase 2: 16 clusters x 8 CTAs. Cluster cid owns batches [cid*4, cid*4+4).
//   CTA rank r owns o in [r*32, r*32+32) for all 4 gates = 128 gate-rows
//   (lr = g*32 + o_l). Weights fully in smem: w4[k4][lr] (ulonglong2, 128KB).
//   256 threads: w = t>>5, l = t&31; kh = w>>2 (k-half), wl = w&3 (gate),
//   b = l&3, lg = l>>2; thread owns rows lr = wl*32 + lg + j*8 (j=0..3),
//   batch b, k in [kh*128, kh*128+128). W LDS.128 serves 8 distinct rows
//   = 128B = 1 wavefront; h loads amortize over 4 rows.
//   k-halves combine via smem; handoff = DSMEM push + mbarrier (as R7).
// ---------------------------------------------------------------------------
// dynamic smem layout (bytes):
//   [0, 131072)           ulonglong2 w4[64][128]
//   [131072, 139392)      float h_s[2][4][260]   (padded: b-stride 1040 B)
//   [139392, 141440)      float4 red[128]        (k-half partials)
//   [141440, 143552)      float gsm[4][132]      (padded)
//   [143552, 143568)      ULL mbar[2]
#define SM_W4   0
#define SM_HS   131072
#define SM_RED  139392
#define SM_GSM  141440
#define SM_MBAR 143552
#define SM_TOTAL 143576
#define HSTRIDE 260
#define GSTRIDE 132

__global__ void __cluster_dims__(8, 1, 1) __launch_bounds__(256, 1)
lstm_rec_kernel(const float* __restrict__ h0, const float* __restrict__ c0,
                const float* __restrict__ Wh, float* __restrict__ out) {
    extern __shared__ __align__(16) unsigned char smraw[];
    ulonglong2* w4 = (ulonglong2*)(smraw + SM_W4);     // [k4][lr]
    float*  h_sf   = (float*)(smraw + SM_HS);          // [p][b][HSTRIDE]
    float4* red    = (float4*)(smraw + SM_RED);        // [wl*32 + l]
    float*  gsm    = (float*)(smraw + SM_GSM);         // [b][GSTRIDE]
    ULL*    mbar   = (ULL*)(smraw + SM_MBAR);

    const int t   = threadIdx.x;
    const int r   = blockIdx.x & 7;        // cluster rank
    const int cid = blockIdx.x >> 3;       // 0..15
    const int w   = t >> 5, l = t & 31;
    const int kh  = w >> 2;                // k-half
    const int wl  = w & 3;                 // gate of this warp's rows
    const int bl  = l & 3;                 // batch
    const int lg  = l >> 2;                // row-group lane
    const int lr0 = wl * 32 + lg;          // rows lr0 + j*8

    // ---- stage W into smem: w4[k4][lr] = Wh[gaterow(lr)][k4*4..+3] ----
    for (int idx = t; idx < 64 * 128; idx += 256) {
        const int k4 = idx >> 7, lr = idx & 127;
        const int grow = (lr >> 5) * 256 + r * 32 + (lr & 31);
        float4 v = *(const float4*)(Wh + (size_t)grow * 256 + k4 * 4);
        w4[k4 * 128 + lr] = *(ulonglong2*)&v;
    }

    // ---- mbarriers + h0 staging (local) ----
    if (t < 2) {
        unsigned mb = smem_u32(&mbar[t]);
        asm volatile("mbarrier.init.shared.b64 [%0], %1;" :: "r"(mb), "r"(8u) : "memory");
    }
    {
        const int b = t >> 6, off = (t & 63) * 4;
        *(float4*)&h_sf[b * HSTRIDE + off] =
            *(const float4*)(h0 + (size_t)(cid * 4 + b) * 256 + off);
    }
    __syncthreads();
    asm volatile("barrier.cluster.arrive.aligned;" ::: "memory");
    asm volatile("barrier.cluster.wait.aligned;" ::: "memory");

    // ---- cell mapping (t<128): o_c = t>>2, b_c = t&3 ----
    const bool cell = (t < 128);
    const int o_c = t >> 2, b_c = t & 3;
    const int o_g = r * 32 + o_c;
    const int b_g = cid * 4 + b_c;
    float creg = cell ? c0[(size_t)b_g * 256 + o_g] : 0.0f;

    float xgv[4];
    if (cell) {
        const float* xp = g_xg + (size_t)(0 * 64 + b_g) * 1024 + o_g;
#pragma unroll
        for (int gg = 0; gg < 4; ++gg) xgv[gg] = __ldcg(xp + gg * 256);
    }

    float* hT = out + (size_t)B_ * S_ * O_;
    float* cT = hT + (size_t)B_ * O_;
    const unsigned hs_base = smem_u32(h_sf);
    const unsigned mb_a[2] = {smem_u32(&mbar[0]), smem_u32(&mbar[1])};
    unsigned par0 = 0, par1 = 0;

    const ulonglong2* wbase = w4 + (size_t)(kh * 32) * 128 + lr0;

    int p = 0;
    for (int s = 0; s < S_; ++s, p ^= 1) {
        if (s > 0) {
            if (p == 0) { mbar_wait_cluster(mb_a[0], par0); par0 ^= 1; }
            else        { mbar_wait_cluster(mb_a[1], par1); par1 ^= 1; }
        }

        // ---- dot: 4 rows x 1 batch x this k-half ----
        const float* hb = h_sf + (p * 4 + bl) * HSTRIDE + kh * 128;
        ULL acc0 = 0ULL, acc1 = 0ULL, acc2 = 0ULL, acc3 = 0ULL;
#pragma unroll 8
        for (int kk = 0; kk < 32; ++kk) {
            const ulonglong2 h2 = *(const ulonglong2*)(hb + kk * 4);
            const ulonglong2 w0 = wbase[kk * 128 + 0];
            const ulonglong2 w1 = wbase[kk * 128 + 8];
            const ulonglong2 w2 = wbase[kk * 128 + 16];
            const ulonglong2 w3 = wbase[kk * 128 + 24];
            acc0 = ffma2(h2.x, w0.x, acc0); acc0 = ffma2(h2.y, w0.y, acc0);
            acc1 = ffma2(h2.x, w1.x, acc1); acc1 = ffma2(h2.y, w1.y, acc1);
            acc2 = ffma2(h2.x, w2.x, acc2); acc2 = ffma2(h2.y, w2.y, acc2);
            acc3 = ffma2(h2.x, w3.x, acc3); acc3 = ffma2(h2.y, w3.y, acc3);
        }
        float p0 = f2lo(acc0) + f2hi(acc0);
        float p1 = f2lo(acc1) + f2hi(acc1);
        float p2 = f2lo(acc2) + f2hi(acc2);
        float p3 = f2lo(acc3) + f2hi(acc3);

        // ---- combine k-halves: kh1 writes partials, kh0 adds + writes gsm ----
        if (kh == 1) red[wl * 32 + l] = make_float4(p0, p1, p2, p3);
        __syncthreads();
        if (kh == 0) {
            const float4 q = red[wl * 32 + l];
            float* gb = gsm + bl * GSTRIDE + wl * 32 + lg;
            gb[0]  = p0 + q.x;
            gb[8]  = p1 + q.y;
            gb[16] = p2 + q.z;
            gb[24] = p3 + q.w;
        }
        __syncthreads();

        // ---- cell update + publish ----
        if (cell) {
            const float* gb = gsm + b_c * GSTRIDE + o_c;
            const float gf = gb[0]  + xgv[0];
            const float gi = gb[32] + xgv[1];
            const float gc = gb[64] + xgv[2];
            const float go = gb[96] + xgv[3];
            const float fg  = sigf(gf);
            const float ig  = sigf(gi);
            const float cg  = tanhx(gc);
            const float ogt = sigf(go);
            creg = creg * fg + ig * cg;
            const float hv = ogt * tanhx(creg);
            out[((size_t)b_g * S_ + s) * 256 + o_g] = hv;
            if (s == S_ - 1) {
                hT[(size_t)b_g * 256 + o_g] = hv;
                cT[(size_t)b_g * 256 + o_g] = creg;
            } else {
                const unsigned dst = hs_base +
                    (unsigned)(((p ^ 1) * 4 + b_c) * HSTRIDE + o_g) * 4u;
#pragma unroll
                for (int rk = 0; rk < 8; ++rk) dsmem_st_f32(dst, rk, hv);
            }
        }
        __syncthreads();   // all pushes issued CTA-wide before release-arrive
        if (s < S_ - 1) {
            if (t < 8) mbar_arrive_rank(mb_a[p ^ 1], t);
            if (cell) {
                const float* xp = g_xg + (size_t)((s + 1) * 64 + b_g) * 1024 + o_g;
#pragma unroll
                for (int gg = 0; gg < 4; ++gg) xgv[gg] = __ldcg(xp + gg * 256);
            }
        }
    }

    asm volatile("barrier.cluster.arrive.aligned;" ::: "memory");
    asm volatile("barrier.cluster.wait.aligned;" ::: "memory");
}

// ---------------------------------------------------------------------------
// launch
// ---------------------------------------------------------------------------
extern "C" void kernel_launch(void* const* d_in, const int* in_sizes, int n_in,
                              void* d_out, int out_size) {
    (void)in_sizes; (void)n_in; (void)out_size;
    const float* x  = (const float*)d_in[0];
    const float* h0 = (const float*)d_in[1];
    const float* c0 = (const float*)d_in[2];
    const float* Wh = (const float*)d_in[3];
    const float* bh = (const float*)d_in[4];
    const float* Wx = (const float*)d_in[5];
    const float* bx = (const float*)d_in[6];
    float* out = (float*)d_out;

    cudaFuncSetAttribute(lstm_rec_kernel,
                         cudaFuncAttributeMaxDynamicSharedMemorySize, SM_TOTAL);

    dim3 g1(1024 / 128, (S_ * B_) / 128);  // (8, 256)
    gemm_xg_kernel<<<g1, 256>>>(x, Wx, bx, bh);
    lstm_rec_kernel<<<128, 256, SM_TOTAL>>>(h0, c0, Wh, out);
}

// round 9
// speedup vs baseline: 1.1559x; 1.1559x over previous
#include <cuda_runtime.h>

#define B_ 64
#define S_ 512
#define I_ 256
#define O_ 256

typedef unsigned long long ULL;

// Scratch: xg[m][n], m = s*64 + b (32768), n = gate*256 + o (1024). 134 MB.
__device__ float g_xg[(size_t)S_ * B_ * 4 * O_];

// ---------------------------------------------------------------------------
// helpers
// ---------------------------------------------------------------------------
__device__ __forceinline__ ULL ffma2(ULL a, ULL b, ULL c) {
    ULL d;
    asm("fma.rn.f32x2 %0, %1, %2, %3;" : "=l"(d) : "l"(a), "l"(b), "l"(c));
    return d;
}
__device__ __forceinline__ float f2lo(ULL v) { return __uint_as_float((unsigned)v); }
__device__ __forceinline__ float f2hi(ULL v) { return __uint_as_float((unsigned)(v >> 32)); }
__device__ __forceinline__ float sigf(float x) { return 1.0f / (1.0f + __expf(-x)); }
__device__ __forceinline__ float tanhx(float x) { return 2.0f * sigf(2.0f * x) - 1.0f; }
__device__ __forceinline__ unsigned smem_u32(const void* p) {
    return (unsigned)__cvta_generic_to_shared(p);
}
__device__ __forceinline__ unsigned mapa_rank(unsigned local_addr, int rank) {
    unsigned ra;
    asm volatile("mapa.shared::cluster.u32 %0, %1, %2;"
                 : "=r"(ra) : "r"(local_addr), "r"(rank));
    return ra;
}
__device__ __forceinline__ void mbar_init(unsigned mbar, unsigned cnt) {
    asm volatile("mbarrier.init.shared.b64 [%0], %1;" :: "r"(mbar), "r"(cnt) : "memory");
}
__device__ __forceinline__ void mbar_arm_tx(unsigned mbar, unsigned tx) {
    asm volatile("mbarrier.arrive.expect_tx.shared.b64 _, [%0], %1;"
                 :: "r"(mbar), "r"(tx) : "memory");
}
__device__ __forceinline__ void mbar_wait_cluster(unsigned mbar, unsigned parity) {
    asm volatile(
        "{\n\t.reg .pred P1;\n\t"
        "WAIT_%=:\n\t"
        "mbarrier.try_wait.parity.acquire.cluster.shared::cta.b64 P1, [%0], %1, 0x989680;\n\t"
        "@P1 bra.uni DONE_%=;\n\t"
        "bra.uni WAIT_%=;\n\t"
        "DONE_%=:\n\t}"
        :: "r"(mbar), "r"(parity) : "memory");
}
// DSM bulk copy: local smem -> peer CTA smem, complete_tx on peer's mbarrier
__device__ __forceinline__ void dsm_bulk_copy(unsigned dst_cluster, unsigned src_cta,
                                              unsigned bytes, unsigned mbar_cluster) {
    asm volatile(
        "cp.async.bulk.shared::cluster.shared::cta.mbarrier::complete_tx::bytes "
        "[%0], [%1], %2, [%3];"
        :: "r"(dst_cluster), "r"(src_cta), "r"(bytes), "r"(mbar_cluster) : "memory");
}

// ---------------------------------------------------------------------------
// Phase 1: xg[m][n] = sum_i x[b,s,i] * Wx[n,i] + bx[n] + bh[n]
//   M=32768 (m=s*64+b), N=1024, K=256. BM=BN=128, BK=16, 256 thr, 8x8 tile.
// ---------------------------------------------------------------------------
__global__ void __launch_bounds__(256, 1) gemm_xg_kernel(
    const float* __restrict__ x, const float* __restrict__ Wx,
    const float* __restrict__ bx, const float* __restrict__ bh) {
    __shared__ __align__(16) float As[128][20];
    __shared__ __align__(16) float Bs[128][20];

    const int t  = threadIdx.x;
    const int bn = blockIdx.x;   // 0..7
    const int bm = blockIdx.y;   // 0..255
    const int tx = t & 15;
    const int ty = t >> 4;

    const int arow  = t & 127;
    const int ahalf = (t >> 7) * 8;            // 0 or 8
    const int m_l   = bm * 128 + arow;
    const float* arp = x + ((size_t)(m_l & 63) * S_ + (m_l >> 6)) * I_ + ahalf;
    const int brow  = t & 127;
    const int bhalf = (t >> 7) * 8;
    const float* brp = Wx + (size_t)(bn * 128 + brow) * I_ + bhalf;

    ULL acc[8][8];
#pragma unroll
    for (int i = 0; i < 8; ++i)
#pragma unroll
        for (int j = 0; j < 8; ++j) acc[i][j] = 0ULL;

    float4 pa0 = *(const float4*)(arp + 0);
    float4 pa1 = *(const float4*)(arp + 4);
    float4 pb0 = *(const float4*)(brp + 0);
    float4 pb1 = *(const float4*)(brp + 4);

    for (int kt = 0; kt < I_; kt += 16) {
        __syncthreads();
        *(float4*)&As[arow][ahalf]     = pa0;
        *(float4*)&As[arow][ahalf + 4] = pa1;
        *(float4*)&Bs[brow][bhalf]     = pb0;
        *(float4*)&Bs[brow][bhalf + 4] = pb1;
        __syncthreads();
        if (kt + 16 < I_) {
            pa0 = *(const float4*)(arp + kt + 16);
            pa1 = *(const float4*)(arp + kt + 20);
            pb0 = *(const float4*)(brp + kt + 16);
            pb1 = *(const float4*)(brp + kt + 20);
        }
#pragma unroll
        for (int k4 = 0; k4 < 4; ++k4) {
            ulonglong2 a2[8];
#pragma unroll
            for (int i = 0; i < 8; ++i)
                a2[i] = *(const ulonglong2*)&As[ty + i * 16][k4 * 4];
#pragma unroll
            for (int j = 0; j < 8; ++j) {
                ulonglong2 b2 = *(const ulonglong2*)&Bs[tx + j * 16][k4 * 4];
#pragma unroll
                for (int i = 0; i < 8; ++i) {
                    acc[i][j] = ffma2(a2[i].x, b2.x, acc[i][j]);
                    acc[i][j] = ffma2(a2[i].y, b2.y, acc[i][j]);
                }
            }
        }
    }

#pragma unroll
    for (int j = 0; j < 8; ++j) {
        const int n = bn * 128 + tx + j * 16;
        const float bias = bx[n] + bh[n];
#pragma unroll
        for (int i = 0; i < 8; ++i) {
            const int m = bm * 128 + ty + i * 16;
            g_xg[(size_t)m * 1024 + n] = f2lo(acc[i][j]) + f2hi(acc[i][j]) + bias;
        }
    }
}

// ---------------------------------------------------------------------------
// Phase 2: 16 clusters x 8 CTAs; cluster owns 4 batches; rank r owns
//   o in [r*32, r*32+32) x 4 gates = 128 gate-rows. Weights in smem (128KB).
//   h buffer layout per parity: 8 rank-blocks x 512B; block = [kk4][b][f4]
//   (value (k,b): block k>>5, offset ((k&31)>>2)*16 + b*4 + (k&3) floats).
//   Handoff: stage own 512B locally, 8x cp.async.bulk DSM copies with
//   complete_tx on receivers' mbarriers (armed with expect_tx=4096).
// ---------------------------------------------------------------------------
// dynamic smem layout (bytes):
//   [0, 131072)        ulonglong2 w4[64][128]
//   [131072, 139264)   float h[2][1024]         (parity x 8 blocks x 512B)
//   [139264, 140288)   float stg[2][128]        (staging, 512B each)
//   [140288, 142336)   float4 red[128]
//   [142336, 144448)   float gsm[4][132]
//   [144448, 144464)   ULL mbar[2]
#define SM_W4    0
#define SM_HS    131072
#define SM_STG   139264
#define SM_RED   140288
#define SM_GSM   142336
#define SM_MBAR  144448
#define SM_TOTAL 144464
#define GSTRIDE  132

__global__ void __cluster_dims__(8, 1, 1) __launch_bounds__(256, 1)
lstm_rec_kernel(const float* __restrict__ h0, const float* __restrict__ c0,
                const float* __restrict__ Wh, float* __restrict__ out) {
    extern __shared__ __align__(16) unsigned char smraw[];
    ulonglong2* w4 = (ulonglong2*)(smraw + SM_W4);     // [k4][lr]
    float*  h_sf   = (float*)(smraw + SM_HS);          // [p][1024]
    float*  stg    = (float*)(smraw + SM_STG);         // [p][128]
    float4* red    = (float4*)(smraw + SM_RED);
    float*  gsm    = (float*)(smraw + SM_GSM);         // [b][GSTRIDE]
    ULL*    mbar   = (ULL*)(smraw + SM_MBAR);

    const int t   = threadIdx.x;
    const int r   = blockIdx.x & 7;        // cluster rank
    const int cid = blockIdx.x >> 3;       // 0..15
    const int w   = t >> 5, l = t & 31;
    const int kh  = w >> 2;                // k-half
    const int wl  = w & 3;                 // gate of this warp's rows
    const int bl  = l & 3;                 // batch
    const int lg  = l >> 2;                // row-group lane
    const int lr0 = wl * 32 + lg;          // rows lr0 + j*8

    // ---- stage W into smem: w4[k4][lr] = Wh[gaterow(lr)][k4*4..+3] ----
    for (int idx = t; idx < 64 * 128; idx += 256) {
        const int k4 = idx >> 7, lr = idx & 127;
        const int grow = (lr >> 5) * 256 + r * 32 + (lr & 31);
        float4 v = *(const float4*)(Wh + (size_t)grow * 256 + k4 * 4);
        w4[k4 * 128 + lr] = *(ulonglong2*)&v;
    }

    const unsigned mb_a[2] = {smem_u32(&mbar[0]), smem_u32(&mbar[1])};
    if (t == 0) {
        mbar_init(mb_a[0], 1u);
        mbar_init(mb_a[1], 1u);
    }
    __syncthreads();
    if (t == 0) {   // pre-arm both phase-0s
        mbar_arm_tx(mb_a[0], 4096u);
        mbar_arm_tx(mb_a[1], 4096u);
    }

    // ---- h0 into parity-0 buffer (blocked layout), all 8 blocks locally ----
    {
        const int k = t;  // 0..255
        const int boff = (k >> 5) * 128 + ((k & 31) >> 2) * 16 + (k & 3);
#pragma unroll
        for (int b = 0; b < 4; ++b)
            h_sf[boff + b * 4] = h0[(size_t)(cid * 4 + b) * 256 + k];
    }
    __syncthreads();
    asm volatile("barrier.cluster.arrive.aligned;" ::: "memory");
    asm volatile("barrier.cluster.wait.aligned;" ::: "memory");

    // ---- cell mapping (t<128): o_c = t>>2, b_c = t&3 ----
    const bool cell = (t < 128);
    const int o_c = t >> 2, b_c = t & 3;
    const int o_g = r * 32 + o_c;
    const int b_g = cid * 4 + b_c;
    float creg = cell ? c0[(size_t)b_g * 256 + o_g] : 0.0f;

    float xgv[4];
    if (cell) {
        const float* xp = g_xg + (size_t)(0 * 64 + b_g) * 1024 + o_g;
#pragma unroll
        for (int gg = 0; gg < 4; ++gg) xgv[gg] = __ldcg(xp + gg * 256);
    }

    float* hT = out + (size_t)B_ * S_ * O_;
    float* cT = hT + (size_t)B_ * O_;
    const unsigned hs_base  = smem_u32(h_sf);
    const unsigned stg_base = smem_u32(stg);
    unsigned par[2] = {0u, 0u};

    int p = 0;
    for (int s = 0; s < S_; ++s, p ^= 1) {
        if (s > 0) {
            mbar_wait_cluster(mb_a[p], par[p]);
            par[p] ^= 1;
            if (t == 0) mbar_arm_tx(mb_a[p], 4096u);  // arm next phase
        }

        // ---- dot: 4 rows (lr0 + j*8) x batch bl x k-half kh ----
        const float* pbase = h_sf + p * 1024 + bl * 4;
        ULL acc0 = 0ULL, acc1 = 0ULL, acc2 = 0ULL, acc3 = 0ULL;
#pragma unroll
        for (int rb = 0; rb < 4; ++rb) {
            const float* hb = pbase + (kh * 4 + rb) * 128;
            const ulonglong2* wb = w4 + (size_t)((kh * 4 + rb) * 8) * 128 + lr0;
#pragma unroll
            for (int kk4 = 0; kk4 < 8; ++kk4) {
                const ulonglong2 h2 = *(const ulonglong2*)(hb + kk4 * 16);
                const ulonglong2 w0 = wb[kk4 * 128 + 0];
                const ulonglong2 w1 = wb[kk4 * 128 + 8];
                const ulonglong2 w2 = wb[kk4 * 128 + 16];
                const ulonglong2 w3 = wb[kk4 * 128 + 24];
                acc0 = ffma2(h2.x, w0.x, acc0); acc0 = ffma2(h2.y, w0.y, acc0);
                acc1 = ffma2(h2.x, w1.x, acc1); acc1 = ffma2(h2.y, w1.y, acc1);
                acc2 = ffma2(h2.x, w2.x, acc2); acc2 = ffma2(h2.y, w2.y, acc2);
                acc3 = ffma2(h2.x, w3.x, acc3); acc3 = ffma2(h2.y, w3.y, acc3);
            }
        }
        float p0 = f2lo(acc0) + f2hi(acc0);
        float p1 = f2lo(acc1) + f2hi(acc1);
        float p2 = f2lo(acc2) + f2hi(acc2);
        float p3 = f2lo(acc3) + f2hi(acc3);

        // ---- combine k-halves ----
        if (kh == 1) red[wl * 32 + l] = make_float4(p0, p1, p2, p3);
        __syncthreads();
        if (kh == 0) {
            const float4 q = red[wl * 32 + l];
            float* gb = gsm + bl * GSTRIDE + wl * 32 + lg;
            gb[0]  = p0 + q.x;
            gb[8]  = p1 + q.y;
            gb[16] = p2 + q.z;
            gb[24] = p3 + q.w;
        }
        __syncthreads();

        // ---- cell update + stage ----
        if (cell) {
            const float* gb = gsm + b_c * GSTRIDE + o_c;
            const float gf = gb[0]  + xgv[0];
            const float gi = gb[32] + xgv[1];
            const float gc = gb[64] + xgv[2];
            const float go = gb[96] + xgv[3];
            const float fg  = sigf(gf);
            const float ig  = sigf(gi);
            const float cg  = tanhx(gc);
            const float ogt = sigf(go);
            creg = creg * fg + ig * cg;
            const float hv = ogt * tanhx(creg);
            out[((size_t)b_g * S_ + s) * 256 + o_g] = hv;
            if (s == S_ - 1) {
                hT[(size_t)b_g * 256 + o_g] = hv;
                cT[(size_t)b_g * 256 + o_g] = creg;
            } else {
                // staging block layout: [(o_c>>2)][b_c][o_c&3]
                stg[(p ^ 1) * 128 + (o_c >> 2) * 16 + b_c * 4 + (o_c & 3)] = hv;
            }
        }
        __syncthreads();   // staging complete CTA-wide

        if (s < S_ - 1) {
            if (t < 8) {
                asm volatile("fence.proxy.async.shared::cta;" ::: "memory");
                const unsigned src = stg_base + (unsigned)(p ^ 1) * 512u;
                const unsigned dst_l = hs_base + (unsigned)((p ^ 1) * 4096 + r * 512);
                const unsigned dst = mapa_rank(dst_l, t);
                const unsigned mbr = mapa_rank(mb_a[p ^ 1], t);
                dsm_bulk_copy(dst, src, 512u, mbr);
            }
            if (cell) {
                const float* xp = g_xg + (size_t)((s + 1) * 64 + b_g) * 1024 + o_g;
#pragma unroll
                for (int gg = 0; gg < 4; ++gg) xgv[gg] = __ldcg(xp + gg * 256);
            }
        }
    }

    asm volatile("barrier.cluster.arrive.aligned;" ::: "memory");
    asm volatile("barrier.cluster.wait.aligned;" ::: "memory");
}

// ---------------------------------------------------------------------------
// launch
// ---------------------------------------------------------------------------
extern "C" void kernel_launch(void* const* d_in, const int* in_sizes, int n_in,
                              void* d_out, int out_size) {
    (void)in_sizes; (void)n_in; (void)out_size;
    const float* x  = (const float*)d_in[0];
    const float* h0 = (const float*)d_in[1];
    const float* c0 = (const float*)d_in[2];
    const float* Wh = (const float*)d_in[3];
    const float* bh = (const float*)d_in[4];
    const float* Wx = (const float*)d_in[5];
    const float* bx = (const float*)d_in[6];
    float* out = (float*)d_out;

    cudaFuncSetAttribute(lstm_rec_kernel,
                         cudaFuncAttributeMaxDynamicSharedMemorySize, SM_TOTAL);

    dim3 g1(1024 / 128, (S_ * B_) / 128);  // (8, 256)
    gemm_xg_kernel<<<g1, 256>>>(x, Wx, bx, bh);
    lstm_rec_kernel<<<128, 256, SM_TOTAL>>>(h0, c0, Wh, out);
}

// round 10
// speedup vs baseline: 1.2204x; 1.0558x over previous
#include <cuda_runtime.h>

#define B_ 64
#define S_ 512
#define I_ 256
#define O_ 256

typedef unsigned long long ULL;

// Scratch: xg[m][n], m = s*64 + b (32768), n = gate*256 + o (1024). 134 MB.
__device__ float g_xg[(size_t)S_ * B_ * 4 * O_];

// ---------------------------------------------------------------------------
// helpers
// ---------------------------------------------------------------------------
__device__ __forceinline__ ULL ffma2(ULL a, ULL b, ULL c) {
    ULL d;
    asm("fma.rn.f32x2 %0, %1, %2, %3;" : "=l"(d) : "l"(a), "l"(b), "l"(c));
    return d;
}
__device__ __forceinline__ float f2lo(ULL v) { return __uint_as_float((unsigned)v); }
__device__ __forceinline__ float f2hi(ULL v) { return __uint_as_float((unsigned)(v >> 32)); }
__device__ __forceinline__ float sigf(float x) { return 1.0f / (1.0f + __expf(-x)); }
__device__ __forceinline__ float tanhx(float x) { return 2.0f * sigf(2.0f * x) - 1.0f; }
__device__ __forceinline__ unsigned smem_u32(const void* p) {
    return (unsigned)__cvta_generic_to_shared(p);
}
__device__ __forceinline__ unsigned mapa_rank(unsigned local_addr, int rank) {
    unsigned ra;
    asm volatile("mapa.shared::cluster.u32 %0, %1, %2;"
                 : "=r"(ra) : "r"(local_addr), "r"(rank));
    return ra;
}
__device__ __forceinline__ void mbar_init(unsigned mbar, unsigned cnt) {
    asm volatile("mbarrier.init.shared.b64 [%0], %1;" :: "r"(mbar), "r"(cnt) : "memory");
}
__device__ __forceinline__ void mbar_arm_tx(unsigned mbar, unsigned tx) {
    asm volatile("mbarrier.arrive.expect_tx.shared.b64 _, [%0], %1;"
                 :: "r"(mbar), "r"(tx) : "memory");
}
__device__ __forceinline__ void mbar_wait_cluster(unsigned mbar, unsigned parity) {
    asm volatile(
        "{\n\t.reg .pred P1;\n\t"
        "WAIT_%=:\n\t"
        "mbarrier.try_wait.parity.acquire.cluster.shared::cta.b64 P1, [%0], %1, 0x989680;\n\t"
        "@P1 bra.uni DONE_%=;\n\t"
        "bra.uni WAIT_%=;\n\t"
        "DONE_%=:\n\t}"
        :: "r"(mbar), "r"(parity) : "memory");
}
// DSM bulk copy: local smem -> peer CTA smem, complete_tx on peer's mbarrier
__device__ __forceinline__ void dsm_bulk_copy(unsigned dst_cluster, unsigned src_cta,
                                              unsigned bytes, unsigned mbar_cluster) {
    asm volatile(
        "cp.async.bulk.shared::cluster.shared::cta.mbarrier::complete_tx::bytes "
        "[%0], [%1], %2, [%3];"
        :: "r"(dst_cluster), "r"(src_cta), "r"(bytes), "r"(mbar_cluster) : "memory");
}

// ---------------------------------------------------------------------------
// Phase 1: xg[m][n] = sum_i x[b,s,i] * Wx[n,i] + bx[n] + bh[n]
//   M=32768 (m=s*64+b), N=1024, K=256. BM=BN=128, BK=16, 256 thr, 8x8 tile.
// ---------------------------------------------------------------------------
__global__ void __launch_bounds__(256, 1) gemm_xg_kernel(
    const float* __restrict__ x, const float* __restrict__ Wx,
    const float* __restrict__ bx, const float* __restrict__ bh) {
    __shared__ __align__(16) float As[128][20];
    __shared__ __align__(16) float Bs[128][20];

    const int t  = threadIdx.x;
    const int bn = blockIdx.x;   // 0..7
    const int bm = blockIdx.y;   // 0..255
    const int tx = t & 15;
    const int ty = t >> 4;

    const int arow  = t & 127;
    const int ahalf = (t >> 7) * 8;            // 0 or 8
    const int m_l   = bm * 128 + arow;
    const float* arp = x + ((size_t)(m_l & 63) * S_ + (m_l >> 6)) * I_ + ahalf;
    const int brow  = t & 127;
    const int bhalf = (t >> 7) * 8;
    const float* brp = Wx + (size_t)(bn * 128 + brow) * I_ + bhalf;

    ULL acc[8][8];
#pragma unroll
    for (int i = 0; i < 8; ++i)
#pragma unroll
        for (int j = 0; j < 8; ++j) acc[i][j] = 0ULL;

    float4 pa0 = *(const float4*)(arp + 0);
    float4 pa1 = *(const float4*)(arp + 4);
    float4 pb0 = *(const float4*)(brp + 0);
    float4 pb1 = *(const float4*)(brp + 4);

    for (int kt = 0; kt < I_; kt += 16) {
        __syncthreads();
        *(float4*)&As[arow][ahalf]     = pa0;
        *(float4*)&As[arow][ahalf + 4] = pa1;
        *(float4*)&Bs[brow][bhalf]     = pb0;
        *(float4*)&Bs[brow][bhalf + 4] = pb1;
        __syncthreads();
        if (kt + 16 < I_) {
            pa0 = *(const float4*)(arp + kt + 16);
            pa1 = *(const float4*)(arp + kt + 20);
            pb0 = *(const float4*)(brp + kt + 16);
            pb1 = *(const float4*)(brp + kt + 20);
        }
#pragma unroll
        for (int k4 = 0; k4 < 4; ++k4) {
            ulonglong2 a2[8];
#pragma unroll
            for (int i = 0; i < 8; ++i)
                a2[i] = *(const ulonglong2*)&As[ty + i * 16][k4 * 4];
#pragma unroll
            for (int j = 0; j < 8; ++j) {
                ulonglong2 b2 = *(const ulonglong2*)&Bs[tx + j * 16][k4 * 4];
#pragma unroll
                for (int i = 0; i < 8; ++i) {
                    acc[i][j] = ffma2(a2[i].x, b2.x, acc[i][j]);
                    acc[i][j] = ffma2(a2[i].y, b2.y, acc[i][j]);
                }
            }
        }
    }

#pragma unroll
    for (int j = 0; j < 8; ++j) {
        const int n = bn * 128 + tx + j * 16;
        const float bias = bx[n] + bh[n];
#pragma unroll
        for (int i = 0; i < 8; ++i) {
            const int m = bm * 128 + ty + i * 16;
            g_xg[(size_t)m * 1024 + n] = f2lo(acc[i][j]) + f2hi(acc[i][j]) + bias;
        }
    }
}

// ---------------------------------------------------------------------------
// Phase 2: 16 clusters x 8 CTAs; cluster owns 4 batches; rank r owns
//   o in [r*32, r*32+32) x 4 gates. Weights in smem (128KB, [k4][lr]).
//   h buffer per parity: 8 rank-blocks x 512B; block = [kk4][b][f4].
//   Pipelined handoff: 16 mbars (rank x parity), each expect_tx=512.
//   Threads consume chunks in rotated order (own first, no wait), waiting
//   each source's mbar just-in-time; cell threads write own block locally;
//   7 bulk copies/step publish to peers.
// ---------------------------------------------------------------------------
// dynamic smem layout (bytes):
//   [0, 131072)        ulonglong2 w4[64][128]
//   [131072, 139264)   float h[2][1024]         (parity x 8 blocks x 512B)
//   [139264, 140288)   float stg[2][128]        (staging, 512B each)
//   [140288, 142336)   float4 red[128]
//   [142336, 144448)   float gsm[4][132]
//   [144448, 144576)   ULL mbar[16]             (idx = rank*2 + parity)
#define SM_W4    0
#define SM_HS    131072
#define SM_STG   139264
#define SM_RED   140288
#define SM_GSM   142336
#define SM_MBAR  144448
#define SM_TOTAL 144576
#define GSTRIDE  132

__global__ void __cluster_dims__(8, 1, 1) __launch_bounds__(256, 1)
lstm_rec_kernel(const float* __restrict__ h0, const float* __restrict__ c0,
                const float* __restrict__ Wh, float* __restrict__ out) {
    extern __shared__ __align__(16) unsigned char smraw[];
    ulonglong2* w4 = (ulonglong2*)(smraw + SM_W4);     // [k4][lr]
    float*  h_sf   = (float*)(smraw + SM_HS);          // [p][1024]
    float*  stg    = (float*)(smraw + SM_STG);         // [p][128]
    float4* red    = (float4*)(smraw + SM_RED);
    float*  gsm    = (float*)(smraw + SM_GSM);         // [b][GSTRIDE]

    const int t   = threadIdx.x;
    const int r   = blockIdx.x & 7;        // cluster rank
    const int cid = blockIdx.x >> 3;       // 0..15
    const int w   = t >> 5, l = t & 31;
    const int kh  = w >> 2;                // k-half
    const int wl  = w & 3;                 // gate of this warp's rows
    const int bl  = l & 3;                 // batch
    const int lg  = l >> 2;                // row-group lane
    const int lr0 = wl * 32 + lg;          // rows lr0 + j*8
    const int kh4 = kh * 4;
    const int rlow = r & 3;

    // ---- stage W into smem: w4[k4][lr] = Wh[gaterow(lr)][k4*4..+3] ----
    for (int idx = t; idx < 64 * 128; idx += 256) {
        const int k4 = idx >> 7, lr = idx & 127;
        const int grow = (lr >> 5) * 256 + r * 32 + (lr & 31);
        float4 v = *(const float4*)(Wh + (size_t)grow * 256 + k4 * 4);
        w4[k4 * 128 + lr] = *(ulonglong2*)&v;
    }

    const unsigned mb_base = smem_u32(smraw + SM_MBAR);
    if (t == 0) {
#pragma unroll
        for (int m = 0; m < 16; ++m) {
            mbar_init(mb_base + m * 8, 1u);
        }
    }
    __syncthreads();
    if (t == 0) {
#pragma unroll
        for (int m = 0; m < 16; ++m) mbar_arm_tx(mb_base + m * 8, 512u);
    }

    // ---- h0 into parity-0 buffer (blocked layout), all 8 blocks locally ----
    {
        const int k = t;  // 0..255
        const int boff = (k >> 5) * 128 + ((k & 31) >> 2) * 16 + (k & 3);
#pragma unroll
        for (int b = 0; b < 4; ++b)
            h_sf[boff + b * 4] = h0[(size_t)(cid * 4 + b) * 256 + k];
    }
    __syncthreads();
    asm volatile("barrier.cluster.arrive.aligned;" ::: "memory");
    asm volatile("barrier.cluster.wait.aligned;" ::: "memory");

    // ---- cell mapping (t<128): o_c = t>>2, b_c = t&3 ----
    const bool cell = (t < 128);
    const int o_c = t >> 2, b_c = t & 3;
    const int o_g = r * 32 + o_c;
    const int b_g = cid * 4 + b_c;
    float creg = cell ? c0[(size_t)b_g * 256 + o_g] : 0.0f;

    // armer assignment: thread arms mbar[armq][p] after consuming it
    int armq = -1;
    if (t < 4) armq = t;
    else if (t >= 128 && t < 132) armq = 4 + (t - 128);
    if (armq == r) armq = -1;

    float xgv[4];
    if (cell) {
        const float* xp = g_xg + (size_t)(0 * 64 + b_g) * 1024 + o_g;
#pragma unroll
        for (int gg = 0; gg < 4; ++gg) xgv[gg] = __ldcg(xp + gg * 256);
    }

    float* hT = out + (size_t)B_ * S_ * O_;
    float* cT = hT + (size_t)B_ * O_;
    const unsigned hs_base  = smem_u32(h_sf);
    const unsigned stg_base = smem_u32(stg);
    unsigned parmask = 0u;  // bit m: expected parity of mbar m

    int p = 0;
    for (int s = 0; s < S_; ++s, p ^= 1) {
        // ---- accumulate over the 4 chunks of this thread's k-half ----
        ULL acc0 = 0ULL, acc1 = 0ULL, acc2 = 0ULL, acc3 = 0ULL;
#pragma unroll
        for (int i = 0; i < 4; ++i) {
            const int rp = kh4 + ((rlow + i) & 3);
            if (s > 0 && rp != r) {
                const int m = rp * 2 + p;
                mbar_wait_cluster(mb_base + m * 8u, (parmask >> m) & 1u);
                parmask ^= (1u << m);
            }
            const float* hb = h_sf + p * 1024 + rp * 128 + bl * 4;
            const ulonglong2* wb = w4 + (size_t)(rp * 8) * 128 + lr0;
#pragma unroll
            for (int kk4 = 0; kk4 < 8; ++kk4) {
                const ulonglong2 h2 = *(const ulonglong2*)(hb + kk4 * 16);
                const ulonglong2 w0 = wb[kk4 * 128 + 0];
                const ulonglong2 w1 = wb[kk4 * 128 + 8];
                const ulonglong2 w2 = wb[kk4 * 128 + 16];
                const ulonglong2 w3 = wb[kk4 * 128 + 24];
                acc0 = ffma2(h2.x, w0.x, acc0); acc0 = ffma2(h2.y, w0.y, acc0);
                acc1 = ffma2(h2.x, w1.x, acc1); acc1 = ffma2(h2.y, w1.y, acc1);
                acc2 = ffma2(h2.x, w2.x, acc2); acc2 = ffma2(h2.y, w2.y, acc2);
                acc3 = ffma2(h2.x, w3.x, acc3); acc3 = ffma2(h2.y, w3.y, acc3);
            }
        }
        // re-arm the mbar this thread is responsible for (consumed this step)
        if (s > 0 && armq >= 0) {
            const int m = armq * 2 + p;
            mbar_arm_tx(mb_base + m * 8u, 512u);
        }

        float p0 = f2lo(acc0) + f2hi(acc0);
        float p1 = f2lo(acc1) + f2hi(acc1);
        float p2 = f2lo(acc2) + f2hi(acc2);
        float p3 = f2lo(acc3) + f2hi(acc3);

        // ---- combine k-halves ----
        if (kh == 1) red[wl * 32 + l] = make_float4(p0, p1, p2, p3);
        __syncthreads();
        if (kh == 0) {
            const float4 q = red[wl * 32 + l];
            float* gb = gsm + bl * GSTRIDE + wl * 32 + lg;
            gb[0]  = p0 + q.x;
            gb[8]  = p1 + q.y;
            gb[16] = p2 + q.z;
            gb[24] = p3 + q.w;
        }
        __syncthreads();

        // ---- cell update + local publish + stage ----
        if (cell) {
            const float* gb = gsm + b_c * GSTRIDE + o_c;
            const float gf = gb[0]  + xgv[0];
            const float gi = gb[32] + xgv[1];
            const float gc = gb[64] + xgv[2];
            const float go = gb[96] + xgv[3];
            const float fg  = sigf(gf);
            const float ig  = sigf(gi);
            const float cg  = tanhx(gc);
            const float ogt = sigf(go);
            creg = creg * fg + ig * cg;
            const float hv = ogt * tanhx(creg);
            out[((size_t)b_g * S_ + s) * 256 + o_g] = hv;
            if (s == S_ - 1) {
                hT[(size_t)b_g * 256 + o_g] = hv;
                cT[(size_t)b_g * 256 + o_g] = creg;
            } else {
                const int boff = (o_c >> 2) * 16 + b_c * 4 + (o_c & 3);
                stg[(p ^ 1) * 128 + boff] = hv;                      // for peers
                h_sf[(p ^ 1) * 1024 + r * 128 + boff] = hv;          // own block
            }
        }
        __syncthreads();   // staging + local write complete CTA-wide

        if (s < S_ - 1) {
            if (t < 8 && t != r) {
                asm volatile("fence.proxy.async.shared::cta;" ::: "memory");
                const unsigned src = stg_base + (unsigned)(p ^ 1) * 512u;
                const unsigned dst_l = hs_base + (unsigned)((p ^ 1) * 4096 + r * 512);
                const unsigned dst = mapa_rank(dst_l, t);
                const unsigned mbr = mapa_rank(mb_base + (unsigned)(r * 2 + (p ^ 1)) * 8u, t);
                dsm_bulk_copy(dst, src, 512u, mbr);
            }
            if (cell) {
                const float* xp = g_xg + (size_t)((s + 1) * 64 + b_g) * 1024 + o_g;
#pragma unroll
                for (int gg = 0; gg < 4; ++gg) xgv[gg] = __ldcg(xp + gg * 256);
            }
        }
    }

    asm volatile("barrier.cluster.arrive.aligned;" ::: "memory");
    asm volatile("barrier.cluster.wait.aligned;" ::: "memory");
}

// ---------------------------------------------------------------------------
// launch
// ---------------------------------------------------------------------------
extern "C" void kernel_launch(void* const* d_in, const int* in_sizes, int n_in,
                              void* d_out, int out_size) {
    (void)in_sizes; (void)n_in; (void)out_size;
    const float* x  = (const float*)d_in[0];
    const float* h0 = (const float*)d_in[1];
    const float* c0 = (const float*)d_in[2];
    const float* Wh = (const float*)d_in[3];
    const float* bh = (const float*)d_in[4];
    const float* Wx = (const float*)d_in[5];
    const float* bx = (const float*)d_in[6];
    float* out = (float*)d_out;

    cudaFuncSetAttribute(lstm_rec_kernel,
                         cudaFuncAttributeMaxDynamicSharedMemorySize, SM_TOTAL);

    dim3 g1(1024 / 128, (S_ * B_) / 128);  // (8, 256)
    gemm_xg_kernel<<<g1, 256>>>(x, Wx, bx, bh);
    lstm_rec_kernel<<<128, 256, SM_TOTAL>>>(h0, c0, Wh, out);
}

// round 11
// speedup vs baseline: 2.1521x; 1.7635x over previous
#include <cuda_runtime.h>

#define B_ 64
#define S_ 512
#define I_ 256
#define O_ 256

typedef unsigned long long ULL;

// Scratch: xg[m][n], m = s*64 + b (32768), n = gate*256 + o (1024). 134 MB.
__device__ float g_xg[(size_t)S_ * B_ * 4 * O_];

// ---------------------------------------------------------------------------
// helpers
// ---------------------------------------------------------------------------
__device__ __forceinline__ ULL ffma2(ULL a, ULL b, ULL c) {
    ULL d;
    asm("fma.rn.f32x2 %0, %1, %2, %3;" : "=l"(d) : "l"(a), "l"(b), "l"(c));
    return d;
}
__device__ __forceinline__ float f2lo(ULL v) { return __uint_as_float((unsigned)v); }
__device__ __forceinline__ float f2hi(ULL v) { return __uint_as_float((unsigned)(v >> 32)); }
__device__ __forceinline__ float sigf(float x) { return 1.0f / (1.0f + __expf(-x)); }
__device__ __forceinline__ float tanhx(float x) { return 2.0f * sigf(2.0f * x) - 1.0f; }
__device__ __forceinline__ unsigned smem_u32(const void* p) {
    return (unsigned)__cvta_generic_to_shared(p);
}
__device__ __forceinline__ unsigned mapa_rank(unsigned local_addr, int rank) {
    unsigned ra;
    asm volatile("mapa.shared::cluster.u32 %0, %1, %2;"
                 : "=r"(ra) : "r"(local_addr), "r"(rank));
    return ra;
}
__device__ __forceinline__ void mbar_init(unsigned mbar, unsigned cnt) {
    asm volatile("mbarrier.init.shared.b64 [%0], %1;" :: "r"(mbar), "r"(cnt) : "memory");
}
__device__ __forceinline__ void mbar_arm_tx(unsigned mbar, unsigned tx) {
    asm volatile("mbarrier.arrive.expect_tx.shared.b64 _, [%0], %1;"
                 :: "r"(mbar), "r"(tx) : "memory");
}
__device__ __forceinline__ void mbar_wait_cluster(unsigned mbar, unsigned parity) {
    asm volatile(
        "{\n\t.reg .pred P1;\n\t"
        "WAIT_%=:\n\t"
        "mbarrier.try_wait.parity.acquire.cluster.shared::cta.b64 P1, [%0], %1, 0x989680;\n\t"
        "@P1 bra.uni DONE_%=;\n\t"
        "bra.uni WAIT_%=;\n\t"
        "DONE_%=:\n\t}"
        :: "r"(mbar), "r"(parity) : "memory");
}
__device__ __forceinline__ void dsm_bulk_copy(unsigned dst_cluster, unsigned src_cta,
                                              unsigned bytes, unsigned mbar_cluster) {
    asm volatile(
        "cp.async.bulk.shared::cluster.shared::cta.mbarrier::complete_tx::bytes "
        "[%0], [%1], %2, [%3];"
        :: "r"(dst_cluster), "r"(src_cta), "r"(bytes), "r"(mbar_cluster) : "memory");
}

// ---------------------------------------------------------------------------
// Phase 1: xg[m][n] = sum_i x[b,s,i] * Wx[n,i] + bx[n] + bh[n]
//   M=32768 (m=s*64+b), N=1024, K=256. BM=BN=128, BK=16, 256 thr, 8x8 tile.
// ---------------------------------------------------------------------------
__global__ void __launch_bounds__(256, 1) gemm_xg_kernel(
    const float* __restrict__ x, const float* __restrict__ Wx,
    const float* __restrict__ bx, const float* __restrict__ bh) {
    __shared__ __align__(16) float As[128][20];
    __shared__ __align__(16) float Bs[128][20];

    const int t  = threadIdx.x;
    const int bn = blockIdx.x;   // 0..7
    const int bm = blockIdx.y;   // 0..255
    const int tx = t & 15;
    const int ty = t >> 4;

    const int arow  = t & 127;
    const int ahalf = (t >> 7) * 8;            // 0 or 8
    const int m_l   = bm * 128 + arow;
    const float* arp = x + ((size_t)(m_l & 63) * S_ + (m_l >> 6)) * I_ + ahalf;
    const int brow  = t & 127;
    const int bhalf = (t >> 7) * 8;
    const float* brp = Wx + (size_t)(bn * 128 + brow) * I_ + bhalf;

    ULL acc[8][8];
#pragma unroll
    for (int i = 0; i < 8; ++i)
#pragma unroll
        for (int j = 0; j < 8; ++j) acc[i][j] = 0ULL;

    float4 pa0 = *(const float4*)(arp + 0);
    float4 pa1 = *(const float4*)(arp + 4);
    float4 pb0 = *(const float4*)(brp + 0);
    float4 pb1 = *(const float4*)(brp + 4);

    for (int kt = 0; kt < I_; kt += 16) {
        __syncthreads();
        *(float4*)&As[arow][ahalf]     = pa0;
        *(float4*)&As[arow][ahalf + 4] = pa1;
        *(float4*)&Bs[brow][bhalf]     = pb0;
        *(float4*)&Bs[brow][bhalf + 4] = pb1;
        __syncthreads();
        if (kt + 16 < I_) {
            pa0 = *(const float4*)(arp + kt + 16);
            pa1 = *(const float4*)(arp + kt + 20);
            pb0 = *(const float4*)(brp + kt + 16);
            pb1 = *(const float4*)(brp + kt + 20);
        }
#pragma unroll
        for (int k4 = 0; k4 < 4; ++k4) {
            ulonglong2 a2[8];
#pragma unroll
            for (int i = 0; i < 8; ++i)
                a2[i] = *(const ulonglong2*)&As[ty + i * 16][k4 * 4];
#pragma unroll
            for (int j = 0; j < 8; ++j) {
                ulonglong2 b2 = *(const ulonglong2*)&Bs[tx + j * 16][k4 * 4];
#pragma unroll
                for (int i = 0; i < 8; ++i) {
                    acc[i][j] = ffma2(a2[i].x, b2.x, acc[i][j]);
                    acc[i][j] = ffma2(a2[i].y, b2.y, acc[i][j]);
                }
            }
        }
    }

#pragma unroll
    for (int j = 0; j < 8; ++j) {
        const int n = bn * 128 + tx + j * 16;
        const float bias = bx[n] + bh[n];
#pragma unroll
        for (int i = 0; i < 8; ++i) {
            const int m = bm * 128 + ty + i * 16;
            g_xg[(size_t)m * 1024 + n] = f2lo(acc[i][j]) + f2hi(acc[i][j]) + bias;
        }
    }
}

// ---------------------------------------------------------------------------
// Phase 2: 32 clusters x 4 CTAs; cluster owns 2 batches; rank r owns
//   o in [r*64, r*64+64) x 4 gates = 256 gate-rows. Thread t = gate-row t,
//   BOTH batches, full k=256. Weight k-blocks (64 k each, rank-rotated):
//   blocks {r, r+1} in registers (64 ULL), blocks {r+2, r+3} in smem 128KB.
//   h per parity: 4 rank-blocks x 512B, block = [k4][b][f4]; broadcast reads.
//   Handoff: stage 512B, 3 bulk copies, per-source mbars, chunk-ordered
//   consumption starting with own block (no wait).
// ---------------------------------------------------------------------------
// dynamic smem (bytes):
//   [0, 131072)        ulonglong2 wS[2][16][256]  ([j][k4][row])
//   [131072, 135168)   float h[2][512]            (parity x 4 blocks x 128 f)
//   [135168, 136192)   float stg[2][128]
//   [136192, 138272)   float gsm[2][260]
//   [138272, 138336)   ULL mbar[8]                (m = src*2 + parity)
#define SM_WS    0
#define SM_HS    131072
#define SM_STG   135168
#define SM_GSM   136192
#define SM_MBAR  138272
#define SM_TOTAL 138336
#define GS       260

__global__ void __cluster_dims__(4, 1, 1) __launch_bounds__(256, 1)
lstm_rec_kernel(const float* __restrict__ h0, const float* __restrict__ c0,
                const float* __restrict__ Wh, float* __restrict__ out) {
    extern __shared__ __align__(16) unsigned char smraw[];
    ulonglong2* wS = (ulonglong2*)(smraw + SM_WS);   // [j*16 + k4][row]
    float* h_sf    = (float*)(smraw + SM_HS);        // [p][512]
    float* stg     = (float*)(smraw + SM_STG);       // [p][128]
    float* gsm     = (float*)(smraw + SM_GSM);       // [b][GS]

    const int t   = threadIdx.x;
    const int r   = blockIdx.x & 3;        // cluster rank
    const int cid = blockIdx.x >> 2;       // 0..31

    // this thread's gate-row: gate = t>>6, o_local = t&63
    const int grow = (t >> 6) * 256 + r * 64 + (t & 63);
    const float* wrow = Wh + (size_t)grow * 256;

    // ---- register weights: blocks {r, (r+1)&3} ----
    ULL wpr[2][32];
#pragma unroll
    for (int j = 0; j < 2; ++j) {
        const int blk = (r + j) & 3;
#pragma unroll
        for (int k2 = 0; k2 < 32; ++k2)
            wpr[j][k2] = *(const ULL*)(wrow + blk * 64 + 2 * k2);
    }

    // ---- smem weights: blocks {(r+2)&3, (r+3)&3}, layout [j][k4][row] ----
    for (int idx = t; idx < 2 * 16 * 256; idx += 256) {
        const int j = idx >> 12, k4 = (idx >> 8) & 15, row = idx & 255;
        const int grw = (row >> 6) * 256 + r * 64 + (row & 63);
        const int blk = (r + 2 + j) & 3;
        float4 v = *(const float4*)(Wh + (size_t)grw * 256 + blk * 64 + k4 * 4);
        wS[(j * 16 + k4) * 256 + row] = *(ulonglong2*)&v;
    }

    const unsigned mb_base = smem_u32(smraw + SM_MBAR);
    if (t == 0) {
#pragma unroll
        for (int m = 0; m < 8; ++m) mbar_init(mb_base + m * 8, 1u);
    }
    __syncthreads();
    if (t == 0) {
#pragma unroll
        for (int src = 0; src < 4; ++src) {
            if (src == r) continue;
            mbar_arm_tx(mb_base + (src * 2 + 0) * 8, 512u);
            mbar_arm_tx(mb_base + (src * 2 + 1) * 8, 512u);
        }
    }

    // ---- h0 into parity-0 buffer (blocked layout) ----
    {
        const int k = t;  // 0..255
        const int rk = k >> 6, kl = k & 63;
        const int base = rk * 128 + (kl >> 2) * 8 + (kl & 3);
#pragma unroll
        for (int b = 0; b < 2; ++b)
            h_sf[base + b * 4] = h0[(size_t)(cid * 2 + b) * 256 + k];
    }
    __syncthreads();
    asm volatile("barrier.cluster.arrive.aligned;" ::: "memory");
    asm volatile("barrier.cluster.wait.aligned;" ::: "memory");

    // ---- cell mapping (t<128): o_c = t>>1, b_c = t&1 ----
    const bool cell = (t < 128);
    const int o_c = t >> 1, b_c = t & 1;
    const int o_g = r * 64 + o_c;
    const int b_g = cid * 2 + b_c;
    float creg = cell ? c0[(size_t)b_g * 256 + o_g] : 0.0f;

    float xgv[4];
    if (cell) {
        const float* xp = g_xg + (size_t)(0 * 64 + b_g) * 1024 + o_g;
#pragma unroll
        for (int gg = 0; gg < 4; ++gg) xgv[gg] = __ldcg(xp + gg * 256);
    }

    float* hT = out + (size_t)B_ * S_ * O_;
    float* cT = hT + (size_t)B_ * O_;
    const unsigned hs_base  = smem_u32(h_sf);
    const unsigned stg_base = smem_u32(stg);
    unsigned parmask = 0u;  // bit m: expected parity of mbar m

    int p = 0;
    for (int s = 0; s < S_; ++s, p ^= 1) {
        const float* hp = h_sf + p * 512;
        ULL acc0 = 0ULL, acc1 = 0ULL;

        // ---- chunk 0: own block r (registers, no wait) ----
        {
            const float* hb = hp + r * 128;
#pragma unroll
            for (int k4 = 0; k4 < 16; ++k4) {
                const ulonglong2 h0v = *(const ulonglong2*)(hb + k4 * 8);
                const ulonglong2 h1v = *(const ulonglong2*)(hb + k4 * 8 + 4);
                acc0 = ffma2(h0v.x, wpr[0][2 * k4], acc0);
                acc0 = ffma2(h0v.y, wpr[0][2 * k4 + 1], acc0);
                acc1 = ffma2(h1v.x, wpr[0][2 * k4], acc1);
                acc1 = ffma2(h1v.y, wpr[0][2 * k4 + 1], acc1);
            }
        }
        // ---- chunk 1: block (r+1)&3 (registers) ----
        {
            const int blk = (r + 1) & 3;
            if (s > 0) {
                const int m = blk * 2 + p;
                mbar_wait_cluster(mb_base + m * 8u, (parmask >> m) & 1u);
                parmask ^= (1u << m);
            }
            const float* hb = hp + blk * 128;
#pragma unroll
            for (int k4 = 0; k4 < 16; ++k4) {
                const ulonglong2 h0v = *(const ulonglong2*)(hb + k4 * 8);
                const ulonglong2 h1v = *(const ulonglong2*)(hb + k4 * 8 + 4);
                acc0 = ffma2(h0v.x, wpr[1][2 * k4], acc0);
                acc0 = ffma2(h0v.y, wpr[1][2 * k4 + 1], acc0);
                acc1 = ffma2(h1v.x, wpr[1][2 * k4], acc1);
                acc1 = ffma2(h1v.y, wpr[1][2 * k4 + 1], acc1);
            }
        }
        // ---- chunks 2,3: blocks (r+2)&3, (r+3)&3 (smem weights) ----
#pragma unroll
        for (int j = 0; j < 2; ++j) {
            const int blk = (r + 2 + j) & 3;
            if (s > 0) {
                const int m = blk * 2 + p;
                mbar_wait_cluster(mb_base + m * 8u, (parmask >> m) & 1u);
                parmask ^= (1u << m);
            }
            const float* hb = hp + blk * 128;
            const ulonglong2* wb = wS + (size_t)(j * 16) * 256 + t;
#pragma unroll
            for (int k4 = 0; k4 < 16; ++k4) {
                const ulonglong2 wv = wb[k4 * 256];
                const ulonglong2 h0v = *(const ulonglong2*)(hb + k4 * 8);
                const ulonglong2 h1v = *(const ulonglong2*)(hb + k4 * 8 + 4);
                acc0 = ffma2(h0v.x, wv.x, acc0);
                acc0 = ffma2(h0v.y, wv.y, acc0);
                acc1 = ffma2(h1v.x, wv.x, acc1);
                acc1 = ffma2(h1v.y, wv.y, acc1);
            }
        }

        // re-arm consumed mbars (one thread per remote source)
        if (s > 0 && t < 3) {
            const int src = (r + 1 + t) & 3;
            mbar_arm_tx(mb_base + (unsigned)(src * 2 + p) * 8u, 512u);
        }

        gsm[t]      = f2lo(acc0) + f2hi(acc0);   // batch 0
        gsm[GS + t] = f2lo(acc1) + f2hi(acc1);   // batch 1
        __syncthreads();

        // ---- cell update + local publish + stage ----
        if (cell) {
            const float* gb = gsm + b_c * GS;
            const float gf = gb[o_c]       + xgv[0];
            const float gi = gb[64 + o_c]  + xgv[1];
            const float gc = gb[128 + o_c] + xgv[2];
            const float go = gb[192 + o_c] + xgv[3];
            const float fg  = sigf(gf);
            const float ig  = sigf(gi);
            const float cg  = tanhx(gc);
            const float ogt = sigf(go);
            creg = creg * fg + ig * cg;
            const float hv = ogt * tanhx(creg);
            out[((size_t)b_g * S_ + s) * 256 + o_g] = hv;
            if (s == S_ - 1) {
                hT[(size_t)b_g * 256 + o_g] = hv;
                cT[(size_t)b_g * 256 + o_g] = creg;
            } else {
                const int q = p ^ 1;
                const int boff = (o_c >> 2) * 8 + b_c * 4 + (o_c & 3);
                stg[q * 128 + boff] = hv;                   // for peers
                h_sf[q * 512 + r * 128 + boff] = hv;        // own block local
            }
        }
        __syncthreads();   // staging + local publish complete CTA-wide

        if (s < S_ - 1) {
            const int q = p ^ 1;
            if (t < 3) {
                asm volatile("fence.proxy.async.shared::cta;" ::: "memory");
                const int dr = (r + 1 + t) & 3;   // destination rank
                const unsigned src = stg_base + (unsigned)q * 512u;
                const unsigned dst_l = hs_base + (unsigned)(q * 512 + r * 128) * 4u;
                const unsigned dst = mapa_rank(dst_l, dr);
                const unsigned mbr = mapa_rank(mb_base + (unsigned)(r * 2 + q) * 8u, dr);
                dsm_bulk_copy(dst, src, 512u, mbr);
            }
            if (cell) {
                const float* xp = g_xg + (size_t)((s + 1) * 64 + b_g) * 1024 + o_g;
#pragma unroll
                for (int gg = 0; gg < 4; ++gg) xgv[gg] = __ldcg(xp + gg * 256);
            }
        }
    }

    asm volatile("barrier.cluster.arrive.aligned;" ::: "memory");
    asm volatile("barrier.cluster.wait.aligned;" ::: "memory");
}

// ---------------------------------------------------------------------------
// launch
// ---------------------------------------------------------------------------
extern "C" void kernel_launch(void* const* d_in, const int* in_sizes, int n_in,
                              void* d_out, int out_size) {
    (void)in_sizes; (void)n_in; (void)out_size;
    const float* x  = (const float*)d_in[0];
    const float* h0 = (const float*)d_in[1];
    const float* c0 = (const float*)d_in[2];
    const float* Wh = (const float*)d_in[3];
    const float* bh = (const float*)d_in[4];
    const float* Wx = (const float*)d_in[5];
    const float* bx = (const float*)d_in[6];
    float* out = (float*)d_out;

    cudaFuncSetAttribute(lstm_rec_kernel,
                         cudaFuncAttributeMaxDynamicSharedMemorySize, SM_TOTAL);

    dim3 g1(1024 / 128, (S_ * B_) / 128);  // (8, 256)
    gemm_xg_kernel<<<g1, 256>>>(x, Wx, bx, bh);
    lstm_rec_kernel<<<128, 256, SM_TOTAL>>>(h0, c0, Wh, out);
}

// round 12
// speedup vs baseline: 2.2150x; 1.0292x over previous
#include <cuda_runtime.h>
#include <cuda_bf16.h>
#include <mma.h>

using namespace nvcuda;

#define B_ 64
#define S_ 512
#define I_ 256
#define O_ 256
#define KP 800   // stacked K': [hi*Whi | lo*Whi | hi*Wlo | bias,0...] padded to 800

typedef unsigned long long ULL;

// Scratch: xg[m][n], m = s*64 + b (32768), n = gate*256 + o (1024). 134 MB.
__device__ float g_xg[(size_t)S_ * B_ * 4 * O_];
// bf16 split operands
__device__ __nv_bfloat16 g_abf[(size_t)32768 * KP];   // 52.4 MB
__device__ __nv_bfloat16 g_bbf[(size_t)1024 * KP];    // 1.6 MB

// ---------------------------------------------------------------------------
// helpers
// ---------------------------------------------------------------------------
__device__ __forceinline__ ULL ffma2(ULL a, ULL b, ULL c) {
    ULL d;
    asm("fma.rn.f32x2 %0, %1, %2, %3;" : "=l"(d) : "l"(a), "l"(b), "l"(c));
    return d;
}
__device__ __forceinline__ float f2lo(ULL v) { return __uint_as_float((unsigned)v); }
__device__ __forceinline__ float f2hi(ULL v) { return __uint_as_float((unsigned)(v >> 32)); }
__device__ __forceinline__ float sigf(float x) { return 1.0f / (1.0f + __expf(-x)); }
__device__ __forceinline__ float tanhx(float x) { return 2.0f * sigf(2.0f * x) - 1.0f; }
__device__ __forceinline__ unsigned smem_u32(const void* p) {
    return (unsigned)__cvta_generic_to_shared(p);
}
__device__ __forceinline__ unsigned mapa_rank(unsigned local_addr, int rank) {
    unsigned ra;
    asm volatile("mapa.shared::cluster.u32 %0, %1, %2;"
                 : "=r"(ra) : "r"(local_addr), "r"(rank));
    return ra;
}
__device__ __forceinline__ void mbar_init(unsigned mbar, unsigned cnt) {
    asm volatile("mbarrier.init.shared.b64 [%0], %1;" :: "r"(mbar), "r"(cnt) : "memory");
}
__device__ __forceinline__ void mbar_arm_tx(unsigned mbar, unsigned tx) {
    asm volatile("mbarrier.arrive.expect_tx.shared.b64 _, [%0], %1;"
                 :: "r"(mbar), "r"(tx) : "memory");
}
__device__ __forceinline__ void mbar_wait_cluster(unsigned mbar, unsigned parity) {
    asm volatile(
        "{\n\t.reg .pred P1;\n\t"
        "WAIT_%=:\n\t"
        "mbarrier.try_wait.parity.acquire.cluster.shared::cta.b64 P1, [%0], %1, 0x989680;\n\t"
        "@P1 bra.uni DONE_%=;\n\t"
        "bra.uni WAIT_%=;\n\t"
        "DONE_%=:\n\t}"
        :: "r"(mbar), "r"(parity) : "memory");
}
__device__ __forceinline__ void dsm_bulk_copy(unsigned dst_cluster, unsigned src_cta,
                                              unsigned bytes, unsigned mbar_cluster) {
    asm volatile(
        "cp.async.bulk.shared::cluster.shared::cta.mbarrier::complete_tx::bytes "
        "[%0], [%1], %2, [%3];"
        :: "r"(dst_cluster), "r"(src_cta), "r"(bytes), "r"(mbar_cluster) : "memory");
}

// ---------------------------------------------------------------------------
// Phase 1a: bf16-split conversion.
//   A'[m][0:256)=hi(x), [256:512)=lo(x), [512:768)=hi(x), [768..769]=1, rest 0
//   (m = s*64 + b; x is [B][S][I])
// ---------------------------------------------------------------------------
__global__ void conv_x_kernel(const float* __restrict__ x) {
    const int m = blockIdx.x;          // 0..32767
    const int t = threadIdx.x;         // 0..255
    const int b = m & 63, s = m >> 6;
    const float f = x[((size_t)b * S_ + s) * I_ + t];
    const __nv_bfloat16 hi = __float2bfloat16(f);
    const __nv_bfloat16 lo = __float2bfloat16(f - __bfloat162float(hi));
    __nv_bfloat16* row = g_abf + (size_t)m * KP;
    row[t]       = hi;
    row[256 + t] = lo;
    row[512 + t] = hi;
    if (t < 32)
        row[768 + t] = __float2bfloat16((t < 2) ? 1.0f : 0.0f);
}

// B'[n][0:256)=hi(W), [256:512)=hi(W), [512:768)=lo(W), [768]=bias_hi,
// [769]=bias_lo, rest 0.   (bias = bx[n] + bh[n])
__global__ void conv_w_kernel(const float* __restrict__ Wx,
                              const float* __restrict__ bx,
                              const float* __restrict__ bh) {
    const int n = blockIdx.x;          // 0..1023
    const int t = threadIdx.x;
    const float f = Wx[(size_t)n * I_ + t];
    const __nv_bfloat16 hi = __float2bfloat16(f);
    const __nv_bfloat16 lo = __float2bfloat16(f - __bfloat162float(hi));
    __nv_bfloat16* row = g_bbf + (size_t)n * KP;
    row[t]       = hi;
    row[256 + t] = hi;
    row[512 + t] = lo;
    if (t < 32) {
        __nv_bfloat16 v = __float2bfloat16(0.0f);
        if (t < 2) {
            const float bias = bx[n] + bh[n];
            const __nv_bfloat16 bhi = __float2bfloat16(bias);
            v = (t == 0) ? bhi : __float2bfloat16(bias - __bfloat162float(bhi));
        }
        row[768 + t] = v;
    }
}

// ---------------------------------------------------------------------------
// Phase 1b: xg = A' (32768 x 800) @ B'^T (800 x 1024) via wmma bf16.
//   BM=BN=128, BK=32, 256 threads, 8 warps (4m x 2n), warp tile 32x64.
//   Grid (8, 256), bn inner => all N-tiles of one M-tile co-run (L2 reuse).
// ---------------------------------------------------------------------------
#define BKG 32
#define KSTAGES (KP / BKG)   // 25

__global__ void __launch_bounds__(256, 1) gemm_bf16_kernel() {
    __shared__ __align__(16) __nv_bfloat16 As[2][128][BKG + 8];
    __shared__ __align__(16) __nv_bfloat16 Bs[2][128][BKG + 8];

    const int t  = threadIdx.x;
    const int bn = blockIdx.x;   // 0..7
    const int bm = blockIdx.y;   // 0..255
    const int wid = t >> 5;
    const int wm = wid & 3;      // 0..3 -> m offset wm*32
    const int wn = wid >> 2;     // 0..1 -> n offset wn*64

    const int row  = t >> 1;     // 0..127
    const int half = t & 1;      // 0/1 -> 16-bf16 halves of a 32-wide k chunk
    const __nv_bfloat16* ag = g_abf + (size_t)(bm * 128 + row) * KP + half * 16;
    const __nv_bfloat16* bg = g_bbf + (size_t)(bn * 128 + row) * KP + half * 16;

    wmma::fragment<wmma::accumulator, 16, 16, 16, float> cf[2][4];
#pragma unroll
    for (int i = 0; i < 2; ++i)
#pragma unroll
        for (int j = 0; j < 4; ++j) wmma::fill_fragment(cf[i][j], 0.0f);

    uint4 pa0 = *(const uint4*)(ag);
    uint4 pa1 = *(const uint4*)(ag + 8);
    uint4 pb0 = *(const uint4*)(bg);
    uint4 pb1 = *(const uint4*)(bg + 8);

    for (int ks = 0; ks < KSTAGES; ++ks) {
        const int cur = ks & 1;
        *(uint4*)&As[cur][row][half * 16]     = pa0;
        *(uint4*)&As[cur][row][half * 16 + 8] = pa1;
        *(uint4*)&Bs[cur][row][half * 16]     = pb0;
        *(uint4*)&Bs[cur][row][half * 16 + 8] = pb1;
        __syncthreads();
        if (ks + 1 < KSTAGES) {
            pa0 = *(const uint4*)(ag + (ks + 1) * BKG);
            pa1 = *(const uint4*)(ag + (ks + 1) * BKG + 8);
            pb0 = *(const uint4*)(bg + (ks + 1) * BKG);
            pb1 = *(const uint4*)(bg + (ks + 1) * BKG + 8);
        }
#pragma unroll
        for (int k16 = 0; k16 < 2; ++k16) {
            wmma::fragment<wmma::matrix_a, 16, 16, 16, __nv_bfloat16,
                           wmma::row_major> af[2];
            wmma::fragment<wmma::matrix_b, 16, 16, 16, __nv_bfloat16,
                           wmma::col_major> bfr[4];
#pragma unroll
            for (int i = 0; i < 2; ++i)
                wmma::load_matrix_sync(af[i],
                    &As[cur][wm * 32 + i * 16][k16 * 16], BKG + 8);
#pragma unroll
            for (int j = 0; j < 4; ++j)
                wmma::load_matrix_sync(bfr[j],
                    &Bs[cur][wn * 64 + j * 16][k16 * 16], BKG + 8);
#pragma unroll
            for (int i = 0; i < 2; ++i)
#pragma unroll
                for (int j = 0; j < 4; ++j)
                    wmma::mma_sync(cf[i][j], af[i], bfr[j], cf[i][j]);
        }
    }

    // epilogue: biases already folded in via k-slots 768/769
#pragma unroll
    for (int i = 0; i < 2; ++i) {
        const int m = bm * 128 + wm * 32 + i * 16;
#pragma unroll
        for (int j = 0; j < 4; ++j) {
            const int n = bn * 128 + wn * 64 + j * 16;
            wmma::store_matrix_sync(g_xg + (size_t)m * 1024 + n, cf[i][j],
                                    1024, wmma::mem_row_major);
        }
    }
}

// ---------------------------------------------------------------------------
// Phase 2: 32 clusters x 4 CTAs (identical to R11 except: bulk copy sources
//   the own h-block directly; staging buffer removed).
// ---------------------------------------------------------------------------
// dynamic smem (bytes):
//   [0, 131072)        ulonglong2 wS[2][16][256]  ([j][k4][row])
//   [131072, 135168)   float h[2][512]            (parity x 4 blocks x 128 f)
//   [135168, 137248)   float gsm[2][260]
//   [137248, 137312)   ULL mbar[8]                (m = src*2 + parity)
#define SM_WS    0
#define SM_HS    131072
#define SM_GSM   135168
#define SM_MBAR  137248
#define SM_TOTAL 137312
#define GS       260

__global__ void __cluster_dims__(4, 1, 1) __launch_bounds__(256, 1)
lstm_rec_kernel(const float* __restrict__ h0, const float* __restrict__ c0,
                const float* __restrict__ Wh, float* __restrict__ out) {
    extern __shared__ __align__(16) unsigned char smraw[];
    ulonglong2* wS = (ulonglong2*)(smraw + SM_WS);   // [j*16 + k4][row]
    float* h_sf    = (float*)(smraw + SM_HS);        // [p][512]
    float* gsm     = (float*)(smraw + SM_GSM);       // [b][GS]

    const int t   = threadIdx.x;
    const int r   = blockIdx.x & 3;        // cluster rank
    const int cid = blockIdx.x >> 2;       // 0..31

    const int grow = (t >> 6) * 256 + r * 64 + (t & 63);
    const float* wrow = Wh + (size_t)grow * 256;

    // register weights: blocks {r, (r+1)&3}
    ULL wpr[2][32];
#pragma unroll
    for (int j = 0; j < 2; ++j) {
        const int blk = (r + j) & 3;
#pragma unroll
        for (int k2 = 0; k2 < 32; ++k2)
            wpr[j][k2] = *(const ULL*)(wrow + blk * 64 + 2 * k2);
    }

    // smem weights: blocks {(r+2)&3, (r+3)&3}, layout [j][k4][row]
    for (int idx = t; idx < 2 * 16 * 256; idx += 256) {
        const int j = idx >> 12, k4 = (idx >> 8) & 15, row = idx & 255;
        const int grw = (row >> 6) * 256 + r * 64 + (row & 63);
        const int blk = (r + 2 + j) & 3;
        float4 v = *(const float4*)(Wh + (size_t)grw * 256 + blk * 64 + k4 * 4);
        wS[(j * 16 + k4) * 256 + row] = *(ulonglong2*)&v;
    }

    const unsigned mb_base = smem_u32(smraw + SM_MBAR);
    if (t == 0) {
#pragma unroll
        for (int m = 0; m < 8; ++m) mbar_init(mb_base + m * 8, 1u);
    }
    __syncthreads();
    if (t == 0) {
#pragma unroll
        for (int src = 0; src < 4; ++src) {
            if (src == r) continue;
            mbar_arm_tx(mb_base + (src * 2 + 0) * 8, 512u);
            mbar_arm_tx(mb_base + (src * 2 + 1) * 8, 512u);
        }
    }

    // h0 into parity-0 buffer (blocked layout)
    {
        const int k = t;
        const int rk = k >> 6, kl = k & 63;
        const int base = rk * 128 + (kl >> 2) * 8 + (kl & 3);
#pragma unroll
        for (int b = 0; b < 2; ++b)
            h_sf[base + b * 4] = h0[(size_t)(cid * 2 + b) * 256 + k];
    }
    __syncthreads();
    asm volatile("barrier.cluster.arrive.aligned;" ::: "memory");
    asm volatile("barrier.cluster.wait.aligned;" ::: "memory");

    const bool cell = (t < 128);
    const int o_c = t >> 1, b_c = t & 1;
    const int o_g = r * 64 + o_c;
    const int b_g = cid * 2 + b_c;
    float creg = cell ? c0[(size_t)b_g * 256 + o_g] : 0.0f;

    float xgv[4];
    if (cell) {
        const float* xp = g_xg + (size_t)(0 * 64 + b_g) * 1024 + o_g;
#pragma unroll
        for (int gg = 0; gg < 4; ++gg) xgv[gg] = __ldcg(xp + gg * 256);
    }

    float* hT = out + (size_t)B_ * S_ * O_;
    float* cT = hT + (size_t)B_ * O_;
    const unsigned hs_base = smem_u32(h_sf);
    unsigned parmask = 0u;

    int p = 0;
    for (int s = 0; s < S_; ++s, p ^= 1) {
        const float* hp = h_sf + p * 512;
        ULL acc0 = 0ULL, acc1 = 0ULL;

        // chunk 0: own block (registers, no wait)
        {
            const float* hb = hp + r * 128;
#pragma unroll
            for (int k4 = 0; k4 < 16; ++k4) {
                const ulonglong2 h0v = *(const ulonglong2*)(hb + k4 * 8);
                const ulonglong2 h1v = *(const ulonglong2*)(hb + k4 * 8 + 4);
                acc0 = ffma2(h0v.x, wpr[0][2 * k4], acc0);
                acc0 = ffma2(h0v.y, wpr[0][2 * k4 + 1], acc0);
                acc1 = ffma2(h1v.x, wpr[0][2 * k4], acc1);
                acc1 = ffma2(h1v.y, wpr[0][2 * k4 + 1], acc1);
            }
        }
        // chunk 1: block (r+1)&3 (registers)
        {
            const int blk = (r + 1) & 3;
            if (s > 0) {
                const int m = blk * 2 + p;
                mbar_wait_cluster(mb_base + m * 8u, (parmask >> m) & 1u);
                parmask ^= (1u << m);
            }
            const float* hb = hp + blk * 128;
#pragma unroll
            for (int k4 = 0; k4 < 16; ++k4) {
                const ulonglong2 h0v = *(const ulonglong2*)(hb + k4 * 8);
                const ulonglong2 h1v = *(const ulonglong2*)(hb + k4 * 8 + 4);
                acc0 = ffma2(h0v.x, wpr[1][2 * k4], acc0);
                acc0 = ffma2(h0v.y, wpr[1][2 * k4 + 1], acc0);
                acc1 = ffma2(h1v.x, wpr[1][2 * k4], acc1);
                acc1 = ffma2(h1v.y, wpr[1][2 * k4 + 1], acc1);
            }
        }
        // chunks 2,3: smem weights
#pragma unroll
        for (int j = 0; j < 2; ++j) {
            const int blk = (r + 2 + j) & 3;
            if (s > 0) {
                const int m = blk * 2 + p;
                mbar_wait_cluster(mb_base + m * 8u, (parmask >> m) & 1u);
                parmask ^= (1u << m);
            }
            const float* hb = hp + blk * 128;
            const ulonglong2* wb = wS + (size_t)(j * 16) * 256 + t;
#pragma unroll
            for (int k4 = 0; k4 < 16; ++k4) {
                const ulonglong2 wv = wb[k4 * 256];
                const ulonglong2 h0v = *(const ulonglong2*)(hb + k4 * 8);
                const ulonglong2 h1v = *(const ulonglong2*)(hb + k4 * 8 + 4);
                acc0 = ffma2(h0v.x, wv.x, acc0);
                acc0 = ffma2(h0v.y, wv.y, acc0);
                acc1 = ffma2(h1v.x, wv.x, acc1);
                acc1 = ffma2(h1v.y, wv.y, acc1);
            }
        }

        if (s > 0 && t < 3) {
            const int src = (r + 1 + t) & 3;
            mbar_arm_tx(mb_base + (unsigned)(src * 2 + p) * 8u, 512u);
        }

        gsm[t]      = f2lo(acc0) + f2hi(acc0);   // batch 0
        gsm[GS + t] = f2lo(acc1) + f2hi(acc1);   // batch 1
        __syncthreads();

        if (cell) {
            const float* gb = gsm + b_c * GS;
            const float gf = gb[o_c]       + xgv[0];
            const float gi = gb[64 + o_c]  + xgv[1];
            const float gc = gb[128 + o_c] + xgv[2];
            const float go = gb[192 + o_c] + xgv[3];
            const float fg  = sigf(gf);
            const float ig  = sigf(gi);
            const float cg  = tanhx(gc);
            const float ogt = sigf(go);
            creg = creg * fg + ig * cg;
            const float hv = ogt * tanhx(creg);
            out[((size_t)b_g * S_ + s) * 256 + o_g] = hv;
            if (s == S_ - 1) {
                hT[(size_t)b_g * 256 + o_g] = hv;
                cT[(size_t)b_g * 256 + o_g] = creg;
            } else {
                const int q = p ^ 1;
                const int boff = (o_c >> 2) * 8 + b_c * 4 + (o_c & 3);
                h_sf[q * 512 + r * 128 + boff] = hv;   // own block (copy src)
            }
        }
        __syncthreads();

        if (s < S_ - 1) {
            const int q = p ^ 1;
            if (t < 3) {
                asm volatile("fence.proxy.async.shared::cta;" ::: "memory");
                const int dr = (r + 1 + t) & 3;
                const unsigned src = hs_base + (unsigned)(q * 512 + r * 128) * 4u;
                const unsigned dst = mapa_rank(src, dr);
                const unsigned mbr = mapa_rank(mb_base + (unsigned)(r * 2 + q) * 8u, dr);
                dsm_bulk_copy(dst, src, 512u, mbr);
            }
            if (cell) {
                const float* xp = g_xg + (size_t)((s + 1) * 64 + b_g) * 1024 + o_g;
#pragma unroll
                for (int gg = 0; gg < 4; ++gg) xgv[gg] = __ldcg(xp + gg * 256);
            }
        }
    }

    asm volatile("barrier.cluster.arrive.aligned;" ::: "memory");
    asm volatile("barrier.cluster.wait.aligned;" ::: "memory");
}

// ---------------------------------------------------------------------------
// launch
// ---------------------------------------------------------------------------
extern "C" void kernel_launch(void* const* d_in, const int* in_sizes, int n_in,
                              void* d_out, int out_size) {
    (void)in_sizes; (void)n_in; (void)out_size;
    const float* x  = (const float*)d_in[0];
    const float* h0 = (const float*)d_in[1];
    const float* c0 = (const float*)d_in[2];
    const float* Wh = (const float*)d_in[3];
    const float* bh = (const float*)d_in[4];
    const float* Wx = (const float*)d_in[5];
    const float* bx = (const float*)d_in[6];
    float* out = (float*)d_out;

    cudaFuncSetAttribute(lstm_rec_kernel,
                         cudaFuncAttributeMaxDynamicSharedMemorySize, SM_TOTAL);

    conv_x_kernel<<<32768, 256>>>(x);
    conv_w_kernel<<<1024, 256>>>(Wx, bx, bh);
    gemm_bf16_kernel<<<dim3(8, 256), 256>>>();
    lstm_rec_kernel<<<128, 256, SM_TOTAL>>>(h0, c0, Wh, out);
}